// round 6
// baseline (speedup 1.0000x reference)
#include <cuda_runtime.h>
#include <cuda_bf16.h>
#include <math.h>
#include <stdint.h>

// Sigma_out[b][i][l] = p_i * p_l * ( S[i][l] - q[i] - r[l] + s )
//   p = softmax(mu[b]) ; q = S p ; r = p^T S ; s = p^T S p
// Persistent-CTA version: grid = 3*148 CTAs, each loops over batches with a
// software pipeline — the next batch's first Sigma/mu loads are issued before
// the current batch's output pass, keeping the DRAM read and write streams
// continuously overlapped instead of phase-bunched per wave.
// Sigma staged in smem with per-row XOR swizzle (all passes conflict-free).
// __ldcs/__stcs: both streams are touch-once -> evict-first in L2.

#define C 128
#define THREADS 256
#define EPT 64          // Sigma elements per thread
#define PF 16           // software-pipelined prefetch depth (registers)
#define CTAS_PER_SM 3
#define NUM_SMS 148

__global__ __launch_bounds__(THREADS, CTAS_PER_SM) void softmax_sigma_kernel(
    const float* __restrict__ mu,       // [B, C]
    const float* __restrict__ Sigma,    // [B, C, C]
    float* __restrict__ mu_out,         // [B, C]
    float* __restrict__ sig_out,        // [B, C, C]
    int B)
{
    const int t = threadIdx.x;
    const int k = t & (C - 1);          // fixed column for this thread
    const int c = t >> 7;               // 0 or 1

    extern __shared__ float sm[];
    float* Ssm   = sm;                  // 16384 swizzled Sigma
    float* psh   = sm + C * C;          // 128  softmax p
    float* pq    = psh + C;             // 128  p_i*(q_i - s)
    float* rtmp  = pq + C;              // 256  r partials (2 per k)
    float* qpart = rtmp + 2 * C;        // 256  q partials (2 per i)
    float* red   = qpart + 2 * C;       // 16   reduction scratch

    int b = blockIdx.x;
    const int stride = gridDim.x;

    // ---- pipeline prologue: first batch's prefetch
    const float* g = Sigma + (size_t)b * (C * C) + t;
    float pf[PF];
    #pragma unroll
    for (int j = 0; j < PF; ++j) pf[j] = __ldcs(g + THREADS * j);
    float xmu = (t < C && b < B) ? mu[b * C + t] : -INFINITY;

    while (b < B) {
        // ---- softmax over mu[b]
        float v = xmu;
        #pragma unroll
        for (int o = 16; o > 0; o >>= 1)
            v = fmaxf(v, __shfl_xor_sync(0xffffffffu, v, o));
        if (t < C && (t & 31) == 0) red[t >> 5] = v;
        __syncthreads();   // also guarantees prior output pass fully done
        float m = fmaxf(fmaxf(red[0], red[1]), fmaxf(red[2], red[3]));
        float e = (t < C) ? expf(xmu - m) : 0.0f;
        v = e;
        #pragma unroll
        for (int o = 16; o > 0; o >>= 1)
            v += __shfl_xor_sync(0xffffffffu, v, o);
        if (t < C && (t & 31) == 0) red[8 + (t >> 5)] = v;
        __syncthreads();
        float denom = red[8] + red[9] + red[10] + red[11];
        if (t < C) {
            float pt = e / denom;
            psh[t] = pt;
            mu_out[b * C + t] = pt;
        }
        __syncthreads();

        // ---- stage Sigma[b] -> smem + r accumulation (k fixed per thread)
        {
            float racc = 0.0f;
            int i = c;
            #pragma unroll
            for (int j = 0; j < EPT; ++j) {
                float val = (j < PF) ? pf[j] : __ldcs(g + THREADS * j);
                Ssm[i * C + (k ^ (i & 31))] = val;
                racc = fmaf(val, psh[i], racc);
                i += 2;
            }
            rtmp[t] = racc;   // rv[k] = rtmp[k] + rtmp[k+128]
        }
        __syncthreads();

        // ---- q pass: thread t -> row i = t&127, k-range [64c, 64c+64)
        {
            const int i  = k;
            const int sw = i & 31;
            const float* row = Ssm + i * C;
            float acc = 0.0f;
            #pragma unroll 8
            for (int kk = 0; kk < 64; ++kk) {
                int kc = 64 * c + kk;     // warp-uniform
                acc = fmaf(row[kc ^ sw], psh[kc], acc);
            }
            qpart[t] = acc;
        }
        __syncthreads();

        // ---- s = p . q ; pq[i] = p_i*(q_i - s)
        float qi = (t < C) ? (qpart[t] + qpart[t + C]) : 0.0f;
        float sv = (t < C) ? psh[t] * qi : 0.0f;
        #pragma unroll
        for (int o = 16; o > 0; o >>= 1)
            sv += __shfl_xor_sync(0xffffffffu, sv, o);
        if (t < C && (t & 31) == 0) red[t >> 5] = sv;
        __syncthreads();
        const float s = red[0] + red[1] + red[2] + red[3];
        if (t < C) pq[t] = psh[t] * (qi - s);

        // ---- pipeline: issue next batch's prefetch BEFORE the output pass
        const int bn = b + stride;
        const float* gn = Sigma + (size_t)bn * (C * C) + t;
        float xmun = -INFINITY;
        if (bn < B) {
            #pragma unroll
            for (int j = 0; j < PF; ++j) pf[j] = __ldcs(gn + THREADS * j);
            if (t < C) xmun = mu[bn * C + t];
        }
        __syncthreads();

        // ---- output: out[i][k] = p_k * ( p_i*(S[i][k] - r_k) - pq[i] )
        {
            const float pk = psh[k];
            const float rk = rtmp[k] + rtmp[k + C];
            float* o = sig_out + (size_t)b * (C * C) + t;
            int i = c;
            #pragma unroll
            for (int j = 0; j < EPT; ++j) {
                float val = Ssm[i * C + (k ^ (i & 31))];
                __stcs(o + THREADS * j,
                       pk * (psh[i] * (val - rk) - pq[i]));
                i += 2;
            }
        }

        b = bn;
        g = gn;
        xmu = xmun;
    }
}

extern "C" void kernel_launch(void* const* d_in, const int* in_sizes, int n_in,
                              void* d_out, int out_size)
{
    // Identify inputs by size: Sigma is C times larger than mu.
    const float* in0 = (const float*)d_in[0];
    const float* in1 = (const float*)d_in[1];
    const float* mu;
    const float* Sigma;
    int B;
    if (in_sizes[0] <= in_sizes[1]) {
        mu = in0; Sigma = in1; B = in_sizes[0] / C;
    } else {
        mu = in1; Sigma = in0; B = in_sizes[1] / C;
    }

    float* mu_out  = (float*)d_out;               // first B*C elements
    float* sig_out = (float*)d_out + (size_t)B * C;

    const int smem = (C * C + 2 * C + 2 * (2 * C) + 16) * sizeof(float);
    cudaFuncSetAttribute(softmax_sigma_kernel,
                         cudaFuncAttributeMaxDynamicSharedMemorySize, smem);

    int grid = NUM_SMS * CTAS_PER_SM;
    if (grid > B) grid = B;
    softmax_sigma_kernel<<<grid, THREADS, smem>>>(mu, Sigma, mu_out, sig_out, B);
}

// round 7
// speedup vs baseline: 1.0705x; 1.0705x over previous
#include <cuda_runtime.h>
#include <cuda_bf16.h>
#include <math.h>
#include <stdint.h>

// Sigma_out[b][i][l] = p_i * p_l * ( S[i][l] - q[i] - r[l] + s )
//   p = softmax(mu[b]) ; q = S p ; r = p^T S ; s = p^T S p
//
// TMA-pipelined version: 1 CTA/SM, double-buffered 64KB cp.async.bulk loads
// of Sigma tiles (issued one batch ahead, mbarrier-completed) so the DRAM
// read stream runs continuously under compute + the STG write stream.
// Smem tiles are plain row-major (bulk copy is contiguous); the q/r pass is
// warp-per-row with shuffle reductions -> all LDS are row-pattern and
// bank-conflict free without any swizzle. Output is scalar coalesced STG.

#define C 128
#define THREADS 256
#define TILE_ELEMS (C * C)            // 16384 floats
#define TILE_BYTES (TILE_ELEMS * 4)   // 65536
#define NUM_SMS 148

// ---- smem float offsets
#define OFF_BUF0  0
#define OFF_BUF1  TILE_ELEMS
#define OFF_PSH   (2 * TILE_ELEMS)          // 128
#define OFF_QSH   (OFF_PSH + C)             // 128
#define OFF_PQ    (OFF_QSH + C)             // 128
#define OFF_RSUM  (OFF_PQ + C)              // 128
#define OFF_RPART (OFF_RSUM + C)            // 8*128 = 1024
#define OFF_RED   (OFF_RPART + 8 * C)       // 16
#define OFF_MBAR  (OFF_RED + 16)            // 4 floats = 16B (2 mbarriers)
#define SMEM_FLOATS (OFF_MBAR + 4)

__device__ __forceinline__ uint32_t smem_u32(const void* p) {
    uint32_t a;
    asm("{ .reg .u64 tmp; cvta.to.shared.u64 tmp, %1; cvt.u32.u64 %0, tmp; }"
        : "=r"(a) : "l"(p));
    return a;
}

__device__ __forceinline__ void mbar_init(uint32_t mbar, uint32_t cnt) {
    asm volatile("mbarrier.init.shared.b64 [%0], %1;" :: "r"(mbar), "r"(cnt) : "memory");
}
__device__ __forceinline__ void mbar_expect_tx(uint32_t mbar, uint32_t bytes) {
    asm volatile("mbarrier.arrive.expect_tx.shared.b64 _, [%0], %1;"
                 :: "r"(mbar), "r"(bytes) : "memory");
}
__device__ __forceinline__ void bulk_load(uint32_t dst, const void* src,
                                          uint32_t bytes, uint32_t mbar) {
    asm volatile(
        "cp.async.bulk.shared::cluster.global.mbarrier::complete_tx::bytes "
        "[%0], [%1], %2, [%3];"
        :: "r"(dst), "l"(src), "r"(bytes), "r"(mbar) : "memory");
}
__device__ __forceinline__ void mbar_wait(uint32_t mbar, uint32_t parity) {
    uint32_t done;
    asm volatile(
        "{\n\t.reg .pred p;\n\t"
        "mbarrier.try_wait.parity.acquire.cta.shared::cta.b64 p, [%1], %2;\n\t"
        "selp.b32 %0, 1, 0, p;\n\t}"
        : "=r"(done) : "r"(mbar), "r"(parity) : "memory");
    if (!done) {
        asm volatile(
            "{\n\t.reg .pred P1;\n\t"
            "WL_%=:\n\t"
            "mbarrier.try_wait.parity.acquire.cta.shared::cta.b64 P1, [%0], %1, 0x989680;\n\t"
            "@P1 bra.uni WD_%=;\n\t"
            "bra.uni WL_%=;\n\t"
            "WD_%=:\n\t}"
            :: "r"(mbar), "r"(parity) : "memory");
    }
}

__global__ __launch_bounds__(THREADS, 1) void softmax_sigma_tma(
    const float* __restrict__ mu,       // [B, C]
    const float* __restrict__ Sigma,    // [B, C, C]
    float* __restrict__ mu_out,         // [B, C]
    float* __restrict__ sig_out,        // [B, C, C]
    int B)
{
    extern __shared__ float sm[];
    float* psh   = sm + OFF_PSH;
    float* qsh   = sm + OFF_QSH;
    float* pq    = sm + OFF_PQ;
    float* rsum  = sm + OFF_RSUM;
    float* rpart = sm + OFF_RPART;
    float* red   = sm + OFF_RED;

    const int t    = threadIdx.x;
    const int w    = t >> 5;
    const int lane = t & 31;
    const int k    = t & (C - 1);
    const int c2   = t >> 7;

    const uint32_t buf_addr[2] = { smem_u32(sm + OFF_BUF0), smem_u32(sm + OFF_BUF1) };
    const uint32_t mbar[2]     = { smem_u32(sm + OFF_MBAR), smem_u32(sm + OFF_MBAR) + 8 };

    if (t == 0) { mbar_init(mbar[0], 1); mbar_init(mbar[1], 1); }
    __syncthreads();

    const int stride = gridDim.x;
    int b   = blockIdx.x;
    int cur = 0;
    uint32_t parity[2] = { 0u, 0u };

    // prologue: first tile load + first mu
    if (t == 0 && b < B) {
        mbar_expect_tx(mbar[0], TILE_BYTES);
        bulk_load(buf_addr[0], Sigma + (size_t)b * TILE_ELEMS, TILE_BYTES, mbar[0]);
    }
    float xmu = (t < C && b < B) ? mu[b * C + t] : -INFINITY;

    while (b < B) {
        const int bn = b + stride;
        const int oth = cur ^ 1;

        // issue NEXT tile load immediately (buffer `oth` was freed by the
        // __syncthreads at the end of the previous iteration)
        if (t == 0 && bn < B) {
            mbar_expect_tx(mbar[oth], TILE_BYTES);
            bulk_load(buf_addr[oth], Sigma + (size_t)bn * TILE_ELEMS, TILE_BYTES, mbar[oth]);
        }
        float xmun = (t < C && bn < B) ? mu[bn * C + t] : -INFINITY;

        // ---- softmax over mu[b] (overlaps with the in-flight TMA load)
        float v = xmu;
        #pragma unroll
        for (int o = 16; o > 0; o >>= 1)
            v = fmaxf(v, __shfl_xor_sync(0xffffffffu, v, o));
        if (t < C && lane == 0) red[w] = v;
        __syncthreads();
        float m = fmaxf(fmaxf(red[0], red[1]), fmaxf(red[2], red[3]));
        float e = (t < C) ? expf(xmu - m) : 0.0f;
        v = e;
        #pragma unroll
        for (int o = 16; o > 0; o >>= 1)
            v += __shfl_xor_sync(0xffffffffu, v, o);
        if (t < C && lane == 0) red[8 + w] = v;
        __syncthreads();
        float denom = red[8] + red[9] + red[10] + red[11];
        if (t < C) {
            float pt = e / denom;
            psh[t] = pt;
            mu_out[b * C + t] = pt;
        }
        __syncthreads();

        // ---- wait for this batch's Sigma tile
        mbar_wait(mbar[cur], parity[cur]);
        parity[cur] ^= 1u;
        const float* bp = sm + (cur ? OFF_BUF1 : OFF_BUF0);

        // ---- fused q/r pass: warp w handles rows i = w + 8*jj
        {
            const float pk0 = psh[lane];
            const float pk1 = psh[lane + 32];
            const float pk2 = psh[lane + 64];
            const float pk3 = psh[lane + 96];
            float r0 = 0.f, r1 = 0.f, r2 = 0.f, r3 = 0.f;
            #pragma unroll
            for (int jj = 0; jj < 16; ++jj) {
                const int i = w + 8 * jj;
                const float* row = bp + i * C;
                float v0 = row[lane], v1 = row[lane + 32];
                float v2 = row[lane + 64], v3 = row[lane + 96];
                float pi = psh[i];
                r0 = fmaf(v0, pi, r0); r1 = fmaf(v1, pi, r1);
                r2 = fmaf(v2, pi, r2); r3 = fmaf(v3, pi, r3);
                float qs = fmaf(v0, pk0, fmaf(v1, pk1, fmaf(v2, pk2, v3 * pk3)));
                #pragma unroll
                for (int o = 16; o > 0; o >>= 1)
                    qs += __shfl_xor_sync(0xffffffffu, qs, o);
                if (lane == jj) qsh[i] = qs;
            }
            rpart[w * C + lane]      = r0;
            rpart[w * C + lane + 32] = r1;
            rpart[w * C + lane + 64] = r2;
            rpart[w * C + lane + 96] = r3;
        }
        __syncthreads();

        // ---- r reduction, s, pq
        float qi = 0.f;
        if (t < C) {
            float rk = 0.f;
            #pragma unroll
            for (int ww = 0; ww < 8; ++ww) rk += rpart[ww * C + t];
            rsum[t] = rk;
            qi = qsh[t];
        }
        float sv = (t < C) ? qi * psh[t] : 0.0f;
        #pragma unroll
        for (int o = 16; o > 0; o >>= 1)
            sv += __shfl_xor_sync(0xffffffffu, sv, o);
        if (t < C && lane == 0) red[w] = sv;
        __syncthreads();
        const float s = red[0] + red[1] + red[2] + red[3];
        if (t < C) pq[t] = psh[t] * (qi - s);
        __syncthreads();

        // ---- output: out[i][k] = p_k * ( p_i*(S[i][k] - r_k) - pq[i] )
        {
            const float pk  = psh[k];
            const float rkv = rsum[k];
            float* o = sig_out + (size_t)b * TILE_ELEMS + t;
            int i = c2;
            #pragma unroll
            for (int j = 0; j < 64; ++j) {
                float val = bp[i * C + k];
                o[THREADS * j] = pk * (psh[i] * (val - rkv) - pq[i]);
                i += 2;
            }
        }
        __syncthreads();   // buffer `cur` free for the load issued next iter

        b = bn; xmu = xmun; cur = oth;
    }
}

// ---------------- fallback: proven round-3 kernel (scalar LDG staging) ----
__global__ __launch_bounds__(THREADS) void softmax_sigma_fallback(
    const float* __restrict__ mu, const float* __restrict__ Sigma,
    float* __restrict__ mu_out, float* __restrict__ sig_out)
{
    const int b = blockIdx.x;
    const int t = threadIdx.x;
    extern __shared__ float sm[];
    float* Ssm = sm; float* p = sm + C * C; float* qv = p + C;
    float* rv = qv + C; float* red = rv + C;
    const float* Sb = Sigma + (size_t)b * (C * C);
    float* Ob = sig_out + (size_t)b * (C * C);

    float x = (t < C) ? mu[b * C + t] : -INFINITY;
    float v = x;
    #pragma unroll
    for (int o = 16; o > 0; o >>= 1) v = fmaxf(v, __shfl_xor_sync(~0u, v, o));
    if (t < C && (t & 31) == 0) red[t >> 5] = v;
    #pragma unroll
    for (int j = 0; j < 64; ++j) {
        int el = t + THREADS * j; int i = el >> 7; int kk = el & (C - 1);
        Ssm[i * C + (kk ^ (i & 31))] = Sb[el];
    }
    __syncthreads();
    float m = fmaxf(fmaxf(red[0], red[1]), fmaxf(red[2], red[3]));
    float e = (t < C) ? expf(x - m) : 0.0f;
    v = e;
    #pragma unroll
    for (int o = 16; o > 0; o >>= 1) v += __shfl_xor_sync(~0u, v, o);
    if (t < C && (t & 31) == 0) red[8 + (t >> 5)] = v;
    __syncthreads();
    float denom = red[8] + red[9] + red[10] + red[11];
    if (t < C) { float pt = e / denom; p[t] = pt; mu_out[b * C + t] = pt; }
    __syncthreads();
    if (t < C) {
        const int i = t, sw = i & 31; const float* row = Ssm + i * C;
        float acc = 0.f;
        #pragma unroll 8
        for (int kk = 0; kk < C; ++kk) acc = fmaf(row[kk ^ sw], p[kk], acc);
        qv[i] = acc;
    } else {
        const int kk = t - C; float acc = 0.f;
        #pragma unroll 8
        for (int i2 = 0; i2 < C; ++i2) acc = fmaf(Ssm[i2 * C + (kk ^ (i2 & 31))], p[i2], acc);
        rv[kk] = acc;
    }
    __syncthreads();
    float sv = (t < C) ? qv[t] * p[t] : 0.f;
    #pragma unroll
    for (int o = 16; o > 0; o >>= 1) sv += __shfl_xor_sync(~0u, sv, o);
    if (t < C && (t & 31) == 0) red[t >> 5] = sv;
    __syncthreads();
    const float s = red[0] + red[1] + red[2] + red[3];
    #pragma unroll
    for (int j = 0; j < 64; ++j) {
        int el = t + THREADS * j; int i = el >> 7; int kk = el & (C - 1);
        float val = Ssm[i * C + (kk ^ (i & 31))];
        Ob[el] = p[i] * p[kk] * (val - rv[kk] - (qv[i] - s));
    }
}

extern "C" void kernel_launch(void* const* d_in, const int* in_sizes, int n_in,
                              void* d_out, int out_size)
{
    const float* in0 = (const float*)d_in[0];
    const float* in1 = (const float*)d_in[1];
    const float* mu; const float* Sigma; int B;
    if (in_sizes[0] <= in_sizes[1]) { mu = in0; Sigma = in1; B = in_sizes[0] / C; }
    else                            { mu = in1; Sigma = in0; B = in_sizes[1] / C; }

    float* mu_out  = (float*)d_out;
    float* sig_out = (float*)d_out + (size_t)B * C;

    if (((uintptr_t)Sigma & 15) == 0) {
        const int smem = SMEM_FLOATS * sizeof(float);   // ~137 KB
        cudaFuncSetAttribute(softmax_sigma_tma,
                             cudaFuncAttributeMaxDynamicSharedMemorySize, smem);
        int grid = NUM_SMS; if (grid > B) grid = B;
        softmax_sigma_tma<<<grid, THREADS, smem>>>(mu, Sigma, mu_out, sig_out, B);
    } else {
        const int smem = (C * C + 3 * C + 16) * sizeof(float);
        cudaFuncSetAttribute(softmax_sigma_fallback,
                             cudaFuncAttributeMaxDynamicSharedMemorySize, smem);
        softmax_sigma_fallback<<<B, THREADS, smem>>>(mu, Sigma, mu_out, sig_out);
    }
}